// round 12
// baseline (speedup 1.0000x reference)
#include <cuda_runtime.h>
#include <cuda_bf16.h>
#include <math.h>
#include <stdint.h>

// Problem constants
#define T_SEQ 256
#define BATCH 64
#define HID   512
#define G4H   2048   // 4*H
#define D2H   1024   // 2*H
#define MR    (T_SEQ*BATCH)   // 16384 rows
#define NBLK_DIR 64

typedef unsigned long long u64;

// ---------------- scratch (device globals: allocation-free) ----------------
__device__ float g_gxf[(size_t)MR * G4H];
__device__ float g_gxb[(size_t)MR * G4H];
__device__ float g_bufA[(size_t)MR * D2H];
__device__ float g_bufB[(size_t)MR * D2H];
__device__ float g_bufC[(size_t)MR * D2H];
__device__ float g_c[2][BATCH * HID];       // [dir][B*H]
__device__ unsigned g_bar[2];               // per-direction grid barrier counters
// bf16 h ping-pong: [dir][pingpong][hi/lo][B*H]
__device__ __nv_bfloat16 g_hbf[2][2][2][BATCH * HID];
// bf16 split scratch for GEMM operands (two A pairs: producers alternate)
__device__ __nv_bfloat16 g_Ahi[(size_t)MR * D2H];
__device__ __nv_bfloat16 g_Alo[(size_t)MR * D2H];
__device__ __nv_bfloat16 g_A2hi[(size_t)MR * D2H];
__device__ __nv_bfloat16 g_A2lo[(size_t)MR * D2H];
__device__ __nv_bfloat16 g_Whi[(size_t)2 * G4H * D2H];
__device__ __nv_bfloat16 g_Wlo[(size_t)2 * G4H * D2H];

__device__ __forceinline__ float* sel_buf(int sel, float* ext) {
    switch (sel) {
        case 1: return g_bufA;
        case 2: return g_bufB;
        case 3: return g_bufC;
        case 4: return g_gxf;
        case 5: return g_gxb;
        default: return ext;
    }
}
__device__ __forceinline__ const float* sel_cbuf(int sel, const float* ext) {
    switch (sel) {
        case 1: return g_bufA;
        case 2: return g_bufB;
        case 3: return g_bufC;
        case 4: return g_gxf;
        case 5: return g_gxb;
        default: return ext;
    }
}

__device__ __forceinline__ float sigf(float x) { return 1.f / (1.f + __expf(-x)); }

__device__ __forceinline__ uint32_t bfpair(float a, float b) {
    __nv_bfloat162 p; p.x = __float2bfloat16(a); p.y = __float2bfloat16(b);
    return *(uint32_t*)&p;
}
__device__ __forceinline__ uint32_t bfpair_lo(float a, float b) {
    float ra = a - __bfloat162float(__float2bfloat16(a));
    float rb = b - __bfloat162float(__float2bfloat16(b));
    return bfpair(ra, rb);
}

// ---------------- bf16 mma.sync (sm_80+ PTX, HMMA on sm_100) --------------
__device__ __forceinline__ void mma16816(float* c, const uint32_t* a, const uint32_t* b)
{
    asm volatile(
        "mma.sync.aligned.m16n8k16.row.col.f32.bf16.bf16.f32 "
        "{%0,%1,%2,%3}, {%4,%5,%6,%7}, {%8,%9}, {%0,%1,%2,%3};"
        : "+f"(c[0]), "+f"(c[1]), "+f"(c[2]), "+f"(c[3])
        : "r"(a[0]), "r"(a[1]), "r"(a[2]), "r"(a[3]), "r"(b[0]), "r"(b[1]));
}

// ---------------- split-bf16 conversion (x + weights only now) -------------
__global__ void split_convert(const float* __restrict__ srcExt, int srcSel,
                              int dstIsW, size_t dstOff, size_t n4)
{
    const float* src = sel_cbuf(srcSel, srcExt);
    __nv_bfloat16* hi = (dstIsW ? g_Whi : g_Ahi) + dstOff;
    __nv_bfloat16* lo = (dstIsW ? g_Wlo : g_Alo) + dstOff;
    size_t i = (size_t)blockIdx.x * blockDim.x + threadIdx.x;
    const size_t stride = (size_t)gridDim.x * blockDim.x;
    for (; i < n4; i += stride) {
        float4 x = *(const float4*)(src + 4 * i);
        __nv_bfloat16 h0 = __float2bfloat16(x.x);
        __nv_bfloat16 h1 = __float2bfloat16(x.y);
        __nv_bfloat16 h2 = __float2bfloat16(x.z);
        __nv_bfloat16 h3 = __float2bfloat16(x.w);
        __nv_bfloat16 l0 = __float2bfloat16(x.x - __bfloat162float(h0));
        __nv_bfloat16 l1 = __float2bfloat16(x.y - __bfloat162float(h1));
        __nv_bfloat16 l2 = __float2bfloat16(x.z - __bfloat162float(h2));
        __nv_bfloat16 l3 = __float2bfloat16(x.w - __bfloat162float(h3));
        __nv_bfloat162* hp = (__nv_bfloat162*)(hi + 4 * i);
        __nv_bfloat162* lp = (__nv_bfloat162*)(lo + 4 * i);
        hp[0] = __nv_bfloat162(h0, h1); hp[1] = __nv_bfloat162(h2, h3);
        lp[0] = __nv_bfloat162(l0, l1); lp[1] = __nv_bfloat162(l2, l3);
    }
}

// ---------------- split-bf16 tensor-core GEMM ------------------------------
// aPair: 1 = read g_Ahi/g_Alo, 2 = read g_A2hi/g_A2lo.
// epiPair (EPI=1 only): 0 = none, 2 = also write bf16 hi/lo of output to pair2.
#define MRS 40
#define MTS (128 * MRS)
#define MBUF (4 * MTS)
#define MG_SMEM (2 * MBUF * 2)

template<int EPI>
__global__ __launch_bounds__(256, 1)
void mma_gemm(const float* __restrict__ bias0, const float* __restrict__ bias1,
              float* C0ext, int c0Sel, float* C1ext, int c1Sel,
              const float* __restrict__ catExt, int catSel,
              const float* __restrict__ prevExt, int prevSel,
              int aPair, int epiPair,
              int N, int K)
{
    extern __shared__ __nv_bfloat16 msm[];
    const int tid  = threadIdx.x;
    const int wid  = tid >> 5;
    const int lane = tid & 31;
    const int z    = blockIdx.z;
    const int n0   = blockIdx.x * 128;
    const int m0   = blockIdx.y * 128;
    const float* bias = z ? bias1 : bias0;
    float* C = z ? sel_buf(c1Sel, C1ext) : sel_buf(c0Sel, C0ext);

    const __nv_bfloat16* Asrc_hi = (aPair == 2) ? g_A2hi : g_Ahi;
    const __nv_bfloat16* Asrc_lo = (aPair == 2) ? g_A2lo : g_Alo;
    const __nv_bfloat16* srcs[4] = {
        Asrc_hi + (size_t)m0 * K,
        Asrc_lo + (size_t)m0 * K,
        g_Whi + (size_t)z * N * K + (size_t)n0 * K,
        g_Wlo + (size_t)z * N * K + (size_t)n0 * K
    };

    const int mw = (wid >> 1) * 32;
    const int nw = (wid & 1) * 64;
    const int r  = lane >> 2;
    const int cq = (lane & 3) * 2;

    float acc[2][8][4] = {};

    uint4 v[8];
    #pragma unroll
    for (int t = 0; t < 4; t++)
        #pragma unroll
        for (int i = 0; i < 2; i++) {
            const int u = i * 256 + tid;
            v[t * 2 + i] = *(const uint4*)(srcs[t] + (size_t)(u >> 2) * K + ((u & 3) * 8));
        }
    #pragma unroll
    for (int t = 0; t < 4; t++)
        #pragma unroll
        for (int i = 0; i < 2; i++) {
            const int u = i * 256 + tid;
            *(uint4*)(msm + t * MTS + (u >> 2) * MRS + (u & 3) * 8) = v[t * 2 + i];
        }
    __syncthreads();

    const int nch = K >> 5;
    for (int ch = 0; ch < nch; ch++) {
        const int b = ch & 1;
        if (ch + 1 < nch) {
            const int koff = (ch + 1) << 5;
            #pragma unroll
            for (int t = 0; t < 4; t++)
                #pragma unroll
                for (int i = 0; i < 2; i++) {
                    const int u = i * 256 + tid;
                    v[t * 2 + i] = *(const uint4*)(srcs[t] + (size_t)(u >> 2) * K + koff + ((u & 3) * 8));
                }
        }
        const __nv_bfloat16* sb = msm + b * MBUF;
        #pragma unroll
        for (int s = 0; s < 2; s++) {
            const int kb = s * 16;
            uint32_t ahi[2][4], alo[2][4];
            #pragma unroll
            for (int mi = 0; mi < 2; mi++) {
                const __nv_bfloat16* ar = sb + (mw + mi * 16 + r) * MRS + kb + cq;
                ahi[mi][0] = *(const uint32_t*)(ar);
                ahi[mi][1] = *(const uint32_t*)(ar + 8 * MRS);
                ahi[mi][2] = *(const uint32_t*)(ar + 8);
                ahi[mi][3] = *(const uint32_t*)(ar + 8 * MRS + 8);
                const __nv_bfloat16* al = ar + MTS;
                alo[mi][0] = *(const uint32_t*)(al);
                alo[mi][1] = *(const uint32_t*)(al + 8 * MRS);
                alo[mi][2] = *(const uint32_t*)(al + 8);
                alo[mi][3] = *(const uint32_t*)(al + 8 * MRS + 8);
            }
            uint32_t bhi[8][2], blo[8][2];
            #pragma unroll
            for (int ni = 0; ni < 8; ni++) {
                const __nv_bfloat16* wr = sb + 2 * MTS + (nw + ni * 8 + r) * MRS + kb + cq;
                bhi[ni][0] = *(const uint32_t*)(wr);
                bhi[ni][1] = *(const uint32_t*)(wr + 8);
                const __nv_bfloat16* wl = wr + MTS;
                blo[ni][0] = *(const uint32_t*)(wl);
                blo[ni][1] = *(const uint32_t*)(wl + 8);
            }
            #pragma unroll
            for (int mi = 0; mi < 2; mi++)
                #pragma unroll
                for (int ni = 0; ni < 8; ni++) {
                    mma16816(acc[mi][ni], ahi[mi], bhi[ni]);
                    mma16816(acc[mi][ni], ahi[mi], blo[ni]);
                    mma16816(acc[mi][ni], alo[mi], bhi[ni]);
                }
        }
        if (ch + 1 < nch) {
            __nv_bfloat16* db = msm + ((ch + 1) & 1) * MBUF;
            #pragma unroll
            for (int t = 0; t < 4; t++)
                #pragma unroll
                for (int i = 0; i < 2; i++) {
                    const int u = i * 256 + tid;
                    *(uint4*)(db + t * MTS + (u >> 2) * MRS + (u & 3) * 8) = v[t * 2 + i];
                }
        }
        __syncthreads();
    }

    float2 bj[8];
    #pragma unroll
    for (int ni = 0; ni < 8; ni++)
        bj[ni] = *(const float2*)(bias + n0 + nw + ni * 8 + cq);

    #pragma unroll
    for (int mi = 0; mi < 2; mi++) {
        #pragma unroll
        for (int half = 0; half < 2; half++) {
            const int m = m0 + mw + mi * 16 + r + half * 8;
            float* crow = C + (size_t)m * N + n0 + nw;
            if (EPI == 0) {
                #pragma unroll
                for (int ni = 0; ni < 8; ni++) {
                    float2 o = make_float2(acc[mi][ni][half * 2 + 0] + bj[ni].x,
                                           acc[mi][ni][half * 2 + 1] + bj[ni].y);
                    *(float2*)(crow + ni * 8 + cq) = o;
                }
            } else {
                const float* catrow  = sel_cbuf(catSel, catExt)   + (size_t)m * N + n0 + nw;
                const float* prevrow = sel_cbuf(prevSel, prevExt) + (size_t)m * N + n0 + nw;
                #pragma unroll
                for (int ni = 0; ni < 8; ni++) {
                    float2 cv = *(const float2*)(catrow + ni * 8 + cq);
                    float2 pv = *(const float2*)(prevrow + ni * 8 + cq);
                    float g0 = 1.f / (1.f + expf(-(acc[mi][ni][half * 2 + 0] + bj[ni].x)));
                    float g1 = 1.f / (1.f + expf(-(acc[mi][ni][half * 2 + 1] + bj[ni].y)));
                    float2 o = make_float2(g0 * cv.x + (1.f - g0) * pv.x,
                                           g1 * cv.y + (1.f - g1) * pv.y);
                    *(float2*)(crow + ni * 8 + cq) = o;
                    if (epiPair == 2) {
                        const size_t ai = (size_t)m * N + n0 + nw + ni * 8 + cq;
                        *(uint32_t*)&g_A2hi[ai] = bfpair(o.x, o.y);
                        *(uint32_t*)&g_A2lo[ai] = bfpair_lo(o.x, o.y);
                    }
                }
            }
        }
    }
}

// ---------------- persistent tensor-core LSTM recurrence -------------------
// grid (64, 2), 256 threads. Block = 8 hidden cols x 4 gates (N=32), M=64.
// 8 warps = 4 m-tiles x 2 k-halves. Whh split-bf16 in smem (once/layer);
// h exchanged via global bf16 hi/lo ping-pong; c in registers.
// Epilogue also writes bf16 hi/lo of the cat output into g_Ahi/g_Alo (pair 1)
// so downstream GEMMs need no separate conversion pass.
#define RWS 520
#define RH_ELE (64 * RWS)
#define W_ELE  (32 * RWS)
#define RED_OFF_ELE (2 * RH_ELE + 2 * W_ELE)
#define PERS2_SMEM (RED_OFF_ELE * 2 + 8192)

__global__ __launch_bounds__(256, 1)
void pers_lstm2(const float* __restrict__ Whf, const float* __restrict__ Whb,
                const float* __restrict__ masks,
                const float* __restrict__ f_init, const float* __restrict__ b_init,
                int layer, int outSel, float* __restrict__ outExt)
{
    extern __shared__ __nv_bfloat16 sm2[];
    __nv_bfloat16* hhi = sm2;
    __nv_bfloat16* hlo = sm2 + RH_ELE;
    __nv_bfloat16* whi = sm2 + 2 * RH_ELE;
    __nv_bfloat16* wlo = whi + W_ELE;
    float* red = (float*)(sm2 + RED_OFF_ELE);

    const int dir = blockIdx.y;
    const float* Whh  = dir ? Whb : Whf;
    const float* gx   = dir ? g_gxb : g_gxf;
    const float* init = (dir ? b_init : f_init) + (size_t)layer * 2 * HID;
    float* outcat = sel_buf(outSel, outExt);

    const int tid = threadIdx.x, lane = tid & 31, wid = tid >> 5;
    const int kh = wid >> 2, mt = wid & 3;
    const int r = lane >> 2, cq = (lane & 3) * 2;
    const int hc0 = blockIdx.x * 8;

    for (int n = 0; n < 32; n++) {
        const float* src = Whh + (size_t)((n >> 3) * HID + hc0 + (n & 7)) * HID;
        for (int k = tid; k < HID; k += 256) {
            float vv = src[k];
            __nv_bfloat16 h = __float2bfloat16(vv);
            whi[n * RWS + k] = h;
            wlo[n * RWS + k] = __float2bfloat16(vv - __bfloat162float(h));
        }
    }

    const int b0 = mt * 16 + r, b1 = b0 + 8;
    const int hcol = hc0 + cq;
    float creg[4];
    creg[0] = init[HID + hcol]; creg[1] = init[HID + hcol + 1];
    creg[2] = creg[0]; creg[3] = creg[1];
    __syncthreads();

    for (int s = 0; s < T_SEQ; s++) {
        const int t = dir ? (T_SEQ - 1 - s) : s;
        const uint4* ghi = (const uint4*)g_hbf[dir][s & 1][0];
        const uint4* glo = (const uint4*)g_hbf[dir][s & 1][1];

        float2 gxv[4][2]; float mk0 = 0.f, mk1 = 0.f;
        if (kh == 0) {
            const size_t gb0 = ((size_t)t * BATCH + b0) * G4H + hcol;
            const size_t gb1 = ((size_t)t * BATCH + b1) * G4H + hcol;
            #pragma unroll
            for (int g = 0; g < 4; g++) {
                gxv[g][0] = __ldcg((const float2*)&gx[gb0 + g * HID]);
                gxv[g][1] = __ldcg((const float2*)&gx[gb1 + g * HID]);
            }
            mk0 = __ldg(&masks[t * BATCH + b0]);
            mk1 = __ldg(&masks[t * BATCH + b1]);
        }

        #pragma unroll
        for (int i = 0; i < 16; i += 4) {
            uint4 va[4], vb[4];
            #pragma unroll
            for (int j = 0; j < 4; j++) {
                const int u = (i + j) * 256 + tid;
                va[j] = __ldcg(ghi + u);
                vb[j] = __ldcg(glo + u);
            }
            #pragma unroll
            for (int j = 0; j < 4; j++) {
                const int u = (i + j) * 256 + tid;
                const int row = u >> 6, c16 = u & 63;
                *(uint4*)(hhi + row * RWS + c16 * 8) = va[j];
                *(uint4*)(hlo + row * RWS + c16 * 8) = vb[j];
            }
        }
        __syncthreads();

        float acc[4][4] = {};
        const int k0 = kh * 256;
        #pragma unroll 4
        for (int ks = 0; ks < 16; ks++) {
            const int kb = k0 + ks * 16;
            const __nv_bfloat16* ar = hhi + (mt * 16 + r) * RWS + kb + cq;
            const __nv_bfloat16* al = hlo + (mt * 16 + r) * RWS + kb + cq;
            uint32_t ahi4[4], alo4[4];
            ahi4[0] = *(const uint32_t*)(ar);
            ahi4[1] = *(const uint32_t*)(ar + 8 * RWS);
            ahi4[2] = *(const uint32_t*)(ar + 8);
            ahi4[3] = *(const uint32_t*)(ar + 8 * RWS + 8);
            alo4[0] = *(const uint32_t*)(al);
            alo4[1] = *(const uint32_t*)(al + 8 * RWS);
            alo4[2] = *(const uint32_t*)(al + 8);
            alo4[3] = *(const uint32_t*)(al + 8 * RWS + 8);
            #pragma unroll
            for (int nt = 0; nt < 4; nt++) {
                const __nv_bfloat16* br = whi + (nt * 8 + r) * RWS + kb + cq;
                const __nv_bfloat16* bl = wlo + (nt * 8 + r) * RWS + kb + cq;
                uint32_t bhi2[2], blo2[2];
                bhi2[0] = *(const uint32_t*)(br); bhi2[1] = *(const uint32_t*)(br + 8);
                blo2[0] = *(const uint32_t*)(bl); blo2[1] = *(const uint32_t*)(bl + 8);
                mma16816(acc[nt], ahi4, bhi2);
                mma16816(acc[nt], ahi4, blo2);
                mma16816(acc[nt], alo4, bhi2);
            }
        }

        if (kh == 1) {
            float4* rr = (float4*)red + ((mt << 5) + lane) * 4;
            #pragma unroll
            for (int nt = 0; nt < 4; nt++)
                rr[nt] = make_float4(acc[nt][0], acc[nt][1], acc[nt][2], acc[nt][3]);
        }
        __syncthreads();

        if (kh == 0) {
            const float4* rr = (const float4*)red + ((mt << 5) + lane) * 4;
            #pragma unroll
            for (int nt = 0; nt < 4; nt++) {
                float4 rv = rr[nt];
                acc[nt][0] += rv.x; acc[nt][1] += rv.y;
                acc[nt][2] += rv.z; acc[nt][3] += rv.w;
            }
            float hn[4];
            #pragma unroll
            for (int j = 0; j < 4; j++) {
                const int bi = j >> 1;
                const float gxi = (j & 1) ? gxv[0][bi].y : gxv[0][bi].x;
                const float gxF = (j & 1) ? gxv[1][bi].y : gxv[1][bi].x;
                const float gxg = (j & 1) ? gxv[2][bi].y : gxv[2][bi].x;
                const float gxo = (j & 1) ? gxv[3][bi].y : gxv[3][bi].x;
                const float mk  = bi ? mk1 : mk0;
                float ig = sigf(acc[0][j] + gxi);
                float fg = sigf(acc[1][j] + gxF);
                float tg = tanhf(acc[2][j] + gxg);
                float og = sigf(acc[3][j] + gxo);
                float cn = (fg * creg[j] + ig * tg) * mk;
                hn[j] = og * tanhf(cn) * mk;
                creg[j] = cn;
            }
            const size_t ob = (size_t)t * (BATCH * D2H) + dir * HID + hcol;
            __stcg((float2*)&outcat[ob + (size_t)b0 * D2H], make_float2(hn[0], hn[1]));
            __stcg((float2*)&outcat[ob + (size_t)b1 * D2H], make_float2(hn[2], hn[3]));
            // fused bf16 split of the cat output (pair 1) for downstream GEMMs
            __stcg((uint32_t*)&g_Ahi[ob + (size_t)b0 * D2H], bfpair(hn[0], hn[1]));
            __stcg((uint32_t*)&g_Alo[ob + (size_t)b0 * D2H], bfpair_lo(hn[0], hn[1]));
            __stcg((uint32_t*)&g_Ahi[ob + (size_t)b1 * D2H], bfpair(hn[2], hn[3]));
            __stcg((uint32_t*)&g_Alo[ob + (size_t)b1 * D2H], bfpair_lo(hn[2], hn[3]));

            __nv_bfloat16* dhi = g_hbf[dir][(s & 1) ^ 1][0];
            __nv_bfloat16* dlo = g_hbf[dir][(s & 1) ^ 1][1];
            #pragma unroll
            for (int half = 0; half < 2; half++) {
                float v0 = hn[half * 2], v1 = hn[half * 2 + 1];
                const int bb = half ? b1 : b0;
                __stcg((uint32_t*)&dhi[bb * HID + hcol], bfpair(v0, v1));
                __stcg((uint32_t*)&dlo[bb * HID + hcol], bfpair_lo(v0, v1));
            }
        }

        __threadfence();
        __syncthreads();
        if (tid == 0) {
            atomicAdd(&g_bar[dir], 1u);
            const unsigned target = (unsigned)NBLK_DIR * (unsigned)(s + 1);
            volatile unsigned* pb = &g_bar[dir];
            while (*pb < target) __nanosleep(32);
        }
        __syncthreads();
    }

    if (kh == 0) {
        *(float2*)&g_c[dir][b0 * HID + hcol] = make_float2(creg[0], creg[1]);
        *(float2*)&g_c[dir][b1 * HID + hcol] = make_float2(creg[2], creg[3]);
    }
}

// ---------------- small state kernels ----------------
__global__ void init_states_kernel(const float* __restrict__ f_init,
                                   const float* __restrict__ b_init, int layer)
{
    int idx = blockIdx.x * blockDim.x + threadIdx.x;
    if (idx < 2 && blockIdx.x == 0) g_bar[idx] = 0;
    if (idx >= BATCH * HID) return;
    int j = idx & (HID - 1);
    float fv = f_init[layer * 2 * HID + j];
    float bv = b_init[layer * 2 * HID + j];
    __nv_bfloat16 fh = __float2bfloat16(fv);
    __nv_bfloat16 bh = __float2bfloat16(bv);
    g_hbf[0][0][0][idx] = fh;
    g_hbf[0][0][1][idx] = __float2bfloat16(fv - __bfloat162float(fh));
    g_hbf[1][0][0][idx] = bh;
    g_hbf[1][0][1][idx] = __float2bfloat16(bv - __bfloat162float(bh));
}

// final h comes from the cat buffer rows (t=255 fwd half, t=0 bwd half)
__global__ void copy_states_kernel(float* __restrict__ hn, float* __restrict__ cn,
                                   int layer, int catSel)
{
    int idx = blockIdx.x * blockDim.x + threadIdx.x;
    if (idx >= BATCH * HID) return;
    int b = idx >> 9, j = idx & (HID - 1);
    const float* cat = sel_cbuf(catSel, nullptr);
    hn[(size_t)(2 * layer + 0) * BATCH * HID + idx] =
        cat[(size_t)(T_SEQ - 1) * (BATCH * D2H) + (size_t)b * D2H + j];
    hn[(size_t)(2 * layer + 1) * BATCH * HID + idx] =
        cat[(size_t)b * D2H + HID + j];
    cn[(size_t)(2 * layer + 0) * BATCH * HID + idx] = g_c[0][idx];
    cn[(size_t)(2 * layer + 1) * BATCH * HID + idx] = g_c[1][idx];
}

// ---------------- launcher ----------------
extern "C" void kernel_launch(void* const* d_in, const int* in_sizes, int n_in,
                              void* d_out, int out_size)
{
    (void)in_sizes; (void)n_in; (void)out_size;
    const float* x          = (const float*)d_in[0];
    const float* masks      = (const float*)d_in[1];
    const float* f_Wih0     = (const float*)d_in[2];
    const float* f_Wih_rest = (const float*)d_in[3];
    const float* f_Whh      = (const float*)d_in[4];
    const float* f_b        = (const float*)d_in[5];
    const float* b_Wih0     = (const float*)d_in[6];
    const float* b_Wih_rest = (const float*)d_in[7];
    const float* b_Whh      = (const float*)d_in[8];
    const float* b_b        = (const float*)d_in[9];
    const float* f_init     = (const float*)d_in[10];
    const float* b_init     = (const float*)d_in[11];
    const float* proj_W     = (const float*)d_in[12];
    const float* proj_b     = (const float*)d_in[13];

    float* out = (float*)d_out;                       // [T,B,2H]
    float* hn  = out + (size_t)MR * D2H;              // [6,B,H]
    float* cn  = hn + (size_t)6 * BATCH * HID;        // [6,B,H]

    cudaFuncSetAttribute(pers_lstm2,
                         cudaFuncAttributeMaxDynamicSharedMemorySize, PERS2_SMEM);
    cudaFuncSetAttribute(mma_gemm<0>,
                         cudaFuncAttributeMaxDynamicSharedMemorySize, MG_SMEM);
    cudaFuncSetAttribute(mma_gemm<1>,
                         cudaFuncAttributeMaxDynamicSharedMemorySize, MG_SMEM);

    const int catSel[3] = { 1, 2, 1 };   // float cat: bufA, bufB, bufA
    const int Kin[3]    = { 512, 1024, 1024 };
    // float "prev" (layer input) for highway: layer1 prev=bufA... careful:
    // layer inputs: L0 = x, L1 = cat0 (bufA), L2 = highway1 out (bufC)
    // A-operand (bf16 pair) for gate GEMM: L0 = pair1(from x), L1 = pair1
    // (pers_lstm2 of L0), L2 = pair2 (highway1 epilogue).
    const int gateAPair[3] = { 1, 1, 2 };

    for (int layer = 0; layer < 3; layer++) {
        const int K = Kin[layer];
        init_states_kernel<<<128, 256>>>(f_init, b_init, layer);

        if (layer == 0)
            split_convert<<<1024, 256>>>(x, 0, 0, 0, ((size_t)MR * K) / 4);
        const float* Wf = (layer == 0) ? f_Wih0 : f_Wih_rest + (size_t)(layer - 1) * G4H * D2H;
        const float* Wb = (layer == 0) ? b_Wih0 : b_Wih_rest + (size_t)(layer - 1) * G4H * D2H;
        split_convert<<<512, 256>>>(Wf, 0, 1, 0,               ((size_t)G4H * K) / 4);
        split_convert<<<512, 256>>>(Wb, 0, 1, (size_t)G4H * K, ((size_t)G4H * K) / 4);

        // ---- gate pre-activations ----
        mma_gemm<0><<<dim3(G4H / 128, MR / 128, 2), 256, MG_SMEM>>>(
            f_b + (size_t)layer * G4H, b_b + (size_t)layer * G4H,
            nullptr, 4 /*gxf*/, nullptr, 5 /*gxb*/,
            nullptr, 0, nullptr, 0,
            gateAPair[layer], 0,
            G4H, K);

        // ---- recurrence (writes cat float + bf16 pair1) ----
        const float* Whf = f_Whh + (size_t)layer * G4H * HID;
        const float* Whb = b_Whh + (size_t)layer * G4H * HID;
        pers_lstm2<<<dim3(NBLK_DIR, 2), 256, PERS2_SMEM>>>(
            Whf, Whb, masks, f_init, b_init, layer, catSel[layer], nullptr);

        copy_states_kernel<<<128, 256>>>(hn, cn, layer, catSel[layer]);

        // ---- highway projection ----
        if (layer > 0) {
            split_convert<<<512, 256>>>(proj_W + (size_t)(layer - 1) * D2H * D2H, 0,
                                        1, 0, ((size_t)D2H * D2H) / 4);
            // prev float buffer: L1 prev = bufA (cat0) — but cat0 was overwritten?
            // No: cat0 lives in bufA; L1's cat is bufB, so bufA still holds L1 input.
            // L2 prev = bufC (highway1 out); L2's cat is bufA (overwrites cat0, ok).
            mma_gemm<1><<<dim3(D2H / 128, MR / 128, 1), 256, MG_SMEM>>>(
                proj_b + (size_t)(layer - 1) * D2H, nullptr,
                (layer == 2) ? out : nullptr, (layer == 1) ? 3 : 0,
                nullptr, 0,
                nullptr, catSel[layer],
                nullptr, (layer == 1) ? 1 : 3,
                1 /*A = pair1 (cat bf16 from pers_lstm2)*/,
                (layer == 1) ? 2 : 0 /*epiPair: write pair2 for L2 gate GEMM*/,
                D2H, D2H);
        }
    }
}

// round 13
// speedup vs baseline: 1.0603x; 1.0603x over previous
#include <cuda_runtime.h>
#include <cuda_bf16.h>
#include <math.h>
#include <stdint.h>

// Problem constants
#define T_SEQ 256
#define BATCH 64
#define HID   512
#define G4H   2048   // 4*H
#define D2H   1024   // 2*H
#define MR    (T_SEQ*BATCH)   // 16384 rows
#define NBLK_DIR 64

typedef unsigned long long u64;

// ---------------- scratch (device globals: allocation-free) ----------------
__device__ float g_gxf[(size_t)MR * G4H];
__device__ float g_gxb[(size_t)MR * G4H];
__device__ float g_bufA[(size_t)MR * D2H];
__device__ float g_bufB[(size_t)MR * D2H];
__device__ float g_bufC[(size_t)MR * D2H];
__device__ float g_c[2][BATCH * HID];       // [dir][B*H]
__device__ unsigned g_bar[2];               // per-direction grid barrier counters
// bf16 h ping-pong: [dir][pingpong][hi/lo][B*H]
__device__ __nv_bfloat16 g_hbf[2][2][2][BATCH * HID];
// bf16 split scratch for GEMM operands (two A pairs: producers alternate)
__device__ __nv_bfloat16 g_Ahi[(size_t)MR * D2H];
__device__ __nv_bfloat16 g_Alo[(size_t)MR * D2H];
__device__ __nv_bfloat16 g_A2hi[(size_t)MR * D2H];
__device__ __nv_bfloat16 g_A2lo[(size_t)MR * D2H];
__device__ __nv_bfloat16 g_Whi[(size_t)2 * G4H * D2H];
__device__ __nv_bfloat16 g_Wlo[(size_t)2 * G4H * D2H];

__device__ __forceinline__ float* sel_buf(int sel, float* ext) {
    switch (sel) {
        case 1: return g_bufA;
        case 2: return g_bufB;
        case 3: return g_bufC;
        case 4: return g_gxf;
        case 5: return g_gxb;
        default: return ext;
    }
}
__device__ __forceinline__ const float* sel_cbuf(int sel, const float* ext) {
    switch (sel) {
        case 1: return g_bufA;
        case 2: return g_bufB;
        case 3: return g_bufC;
        case 4: return g_gxf;
        case 5: return g_gxb;
        default: return ext;
    }
}

__device__ __forceinline__ float sigf(float x) { return 1.f / (1.f + __expf(-x)); }

__device__ __forceinline__ uint32_t bfpair(float a, float b) {
    __nv_bfloat162 p; p.x = __float2bfloat16(a); p.y = __float2bfloat16(b);
    return *(uint32_t*)&p;
}
__device__ __forceinline__ uint32_t bfpair_lo(float a, float b) {
    float ra = a - __bfloat162float(__float2bfloat16(a));
    float rb = b - __bfloat162float(__float2bfloat16(b));
    return bfpair(ra, rb);
}

// ---------------- bf16 mma.sync (sm_80+ PTX, HMMA on sm_100) --------------
__device__ __forceinline__ void mma16816(float* c, const uint32_t* a, const uint32_t* b)
{
    asm volatile(
        "mma.sync.aligned.m16n8k16.row.col.f32.bf16.bf16.f32 "
        "{%0,%1,%2,%3}, {%4,%5,%6,%7}, {%8,%9}, {%0,%1,%2,%3};"
        : "+f"(c[0]), "+f"(c[1]), "+f"(c[2]), "+f"(c[3])
        : "r"(a[0]), "r"(a[1]), "r"(a[2]), "r"(a[3]), "r"(b[0]), "r"(b[1]));
}

__device__ __forceinline__ void cp16(uint32_t daddr, const void* g) {
    asm volatile("cp.async.cg.shared.global [%0], [%1], 16;" :: "r"(daddr), "l"(g));
}

// ---------------- split-bf16 conversion (x + weights only) -----------------
__global__ void split_convert(const float* __restrict__ srcExt, int srcSel,
                              int dstIsW, size_t dstOff, size_t n4)
{
    const float* src = sel_cbuf(srcSel, srcExt);
    __nv_bfloat16* hi = (dstIsW ? g_Whi : g_Ahi) + dstOff;
    __nv_bfloat16* lo = (dstIsW ? g_Wlo : g_Alo) + dstOff;
    size_t i = (size_t)blockIdx.x * blockDim.x + threadIdx.x;
    const size_t stride = (size_t)gridDim.x * blockDim.x;
    for (; i < n4; i += stride) {
        float4 x = *(const float4*)(src + 4 * i);
        __nv_bfloat16 h0 = __float2bfloat16(x.x);
        __nv_bfloat16 h1 = __float2bfloat16(x.y);
        __nv_bfloat16 h2 = __float2bfloat16(x.z);
        __nv_bfloat16 h3 = __float2bfloat16(x.w);
        __nv_bfloat16 l0 = __float2bfloat16(x.x - __bfloat162float(h0));
        __nv_bfloat16 l1 = __float2bfloat16(x.y - __bfloat162float(h1));
        __nv_bfloat16 l2 = __float2bfloat16(x.z - __bfloat162float(h2));
        __nv_bfloat16 l3 = __float2bfloat16(x.w - __bfloat162float(h3));
        __nv_bfloat162* hp = (__nv_bfloat162*)(hi + 4 * i);
        __nv_bfloat162* lp = (__nv_bfloat162*)(lo + 4 * i);
        hp[0] = __nv_bfloat162(h0, h1); hp[1] = __nv_bfloat162(h2, h3);
        lp[0] = __nv_bfloat162(l0, l1); lp[1] = __nv_bfloat162(l2, l3);
    }
}

// ---------------- split-bf16 tensor-core GEMM (cp.async, occupancy 2) ------
#define MRS 40
#define MTS (128 * MRS)
#define MBUF (4 * MTS)
#define MG_SMEM (2 * MBUF * 2)

template<int EPI>
__global__ __launch_bounds__(256, 2)
void mma_gemm(const float* __restrict__ bias0, const float* __restrict__ bias1,
              float* C0ext, int c0Sel, float* C1ext, int c1Sel,
              const float* __restrict__ catExt, int catSel,
              const float* __restrict__ prevExt, int prevSel,
              int aPair, int epiPair,
              int N, int K)
{
    extern __shared__ __nv_bfloat16 msm[];
    const int tid  = threadIdx.x;
    const int wid  = tid >> 5;
    const int lane = tid & 31;
    const int z    = blockIdx.z;
    const int n0   = blockIdx.x * 128;
    const int m0   = blockIdx.y * 128;
    const float* bias = z ? bias1 : bias0;
    float* C = z ? sel_buf(c1Sel, C1ext) : sel_buf(c0Sel, C0ext);

    const __nv_bfloat16* Asrc_hi = (aPair == 2) ? g_A2hi : g_Ahi;
    const __nv_bfloat16* Asrc_lo = (aPair == 2) ? g_A2lo : g_Alo;
    const __nv_bfloat16* srcs[4] = {
        Asrc_hi + (size_t)m0 * K,
        Asrc_lo + (size_t)m0 * K,
        g_Whi + (size_t)z * N * K + (size_t)n0 * K,
        g_Wlo + (size_t)z * N * K + (size_t)n0 * K
    };

    const int mw = (wid >> 1) * 32;
    const int nw = (wid & 1) * 64;
    const int r  = lane >> 2;
    const int cq = (lane & 3) * 2;

    const uint32_t sbase = (uint32_t)__cvta_generic_to_shared(msm);
    const int lrow = tid >> 2, lcolu = tid & 3;

    float acc[2][8][4] = {};
    const int nch = K >> 5;

    // prologue: async-load chunk 0
    {
        #pragma unroll
        for (int t = 0; t < 4; t++)
            #pragma unroll
            for (int i = 0; i < 2; i++) {
                const int row = lrow + i * 64;
                cp16(sbase + (uint32_t)(t * MTS + row * MRS + lcolu * 8) * 2,
                     srcs[t] + (size_t)row * K + lcolu * 8);
            }
        asm volatile("cp.async.commit_group;");
    }

    for (int ch = 0; ch < nch; ch++) {
        if (ch + 1 < nch) {
            const int koff = (ch + 1) << 5;
            const int bb = (ch + 1) & 1;
            #pragma unroll
            for (int t = 0; t < 4; t++)
                #pragma unroll
                for (int i = 0; i < 2; i++) {
                    const int row = lrow + i * 64;
                    cp16(sbase + (uint32_t)(bb * MBUF + t * MTS + row * MRS + lcolu * 8) * 2,
                         srcs[t] + (size_t)row * K + koff + lcolu * 8);
                }
            asm volatile("cp.async.commit_group;");
            asm volatile("cp.async.wait_group 1;");
        } else {
            asm volatile("cp.async.wait_group 0;");
        }
        __syncthreads();

        const __nv_bfloat16* sb = msm + (ch & 1) * MBUF;
        #pragma unroll
        for (int s = 0; s < 2; s++) {
            const int kb = s * 16;
            uint32_t ahi[2][4], alo[2][4];
            #pragma unroll
            for (int mi = 0; mi < 2; mi++) {
                const __nv_bfloat16* ar = sb + (mw + mi * 16 + r) * MRS + kb + cq;
                ahi[mi][0] = *(const uint32_t*)(ar);
                ahi[mi][1] = *(const uint32_t*)(ar + 8 * MRS);
                ahi[mi][2] = *(const uint32_t*)(ar + 8);
                ahi[mi][3] = *(const uint32_t*)(ar + 8 * MRS + 8);
                const __nv_bfloat16* al = ar + MTS;
                alo[mi][0] = *(const uint32_t*)(al);
                alo[mi][1] = *(const uint32_t*)(al + 8 * MRS);
                alo[mi][2] = *(const uint32_t*)(al + 8);
                alo[mi][3] = *(const uint32_t*)(al + 8 * MRS + 8);
            }
            #pragma unroll
            for (int nh = 0; nh < 2; nh++) {
                uint32_t bhi[4][2], blo[4][2];
                #pragma unroll
                for (int nj = 0; nj < 4; nj++) {
                    const int ni = nh * 4 + nj;
                    const __nv_bfloat16* wr = sb + 2 * MTS + (nw + ni * 8 + r) * MRS + kb + cq;
                    bhi[nj][0] = *(const uint32_t*)(wr);
                    bhi[nj][1] = *(const uint32_t*)(wr + 8);
                    const __nv_bfloat16* wl = wr + MTS;
                    blo[nj][0] = *(const uint32_t*)(wl);
                    blo[nj][1] = *(const uint32_t*)(wl + 8);
                }
                #pragma unroll
                for (int mi = 0; mi < 2; mi++)
                    #pragma unroll
                    for (int nj = 0; nj < 4; nj++) {
                        const int ni = nh * 4 + nj;
                        mma16816(acc[mi][ni], ahi[mi], bhi[nj]);
                        mma16816(acc[mi][ni], ahi[mi], blo[nj]);
                        mma16816(acc[mi][ni], alo[mi], bhi[nj]);
                    }
            }
        }
        __syncthreads();
    }

    float2 bj[8];
    #pragma unroll
    for (int ni = 0; ni < 8; ni++)
        bj[ni] = *(const float2*)(bias + n0 + nw + ni * 8 + cq);

    #pragma unroll
    for (int mi = 0; mi < 2; mi++) {
        #pragma unroll
        for (int half = 0; half < 2; half++) {
            const int m = m0 + mw + mi * 16 + r + half * 8;
            float* crow = C + (size_t)m * N + n0 + nw;
            if (EPI == 0) {
                #pragma unroll
                for (int ni = 0; ni < 8; ni++) {
                    float2 o = make_float2(acc[mi][ni][half * 2 + 0] + bj[ni].x,
                                           acc[mi][ni][half * 2 + 1] + bj[ni].y);
                    *(float2*)(crow + ni * 8 + cq) = o;
                }
            } else {
                const float* catrow  = sel_cbuf(catSel, catExt)   + (size_t)m * N + n0 + nw;
                const float* prevrow = sel_cbuf(prevSel, prevExt) + (size_t)m * N + n0 + nw;
                #pragma unroll
                for (int ni = 0; ni < 8; ni++) {
                    float2 cv = *(const float2*)(catrow + ni * 8 + cq);
                    float2 pv = *(const float2*)(prevrow + ni * 8 + cq);
                    float g0 = 1.f / (1.f + expf(-(acc[mi][ni][half * 2 + 0] + bj[ni].x)));
                    float g1 = 1.f / (1.f + expf(-(acc[mi][ni][half * 2 + 1] + bj[ni].y)));
                    float2 o = make_float2(g0 * cv.x + (1.f - g0) * pv.x,
                                           g1 * cv.y + (1.f - g1) * pv.y);
                    *(float2*)(crow + ni * 8 + cq) = o;
                    if (epiPair == 2) {
                        const size_t ai = (size_t)m * N + n0 + nw + ni * 8 + cq;
                        *(uint32_t*)&g_A2hi[ai] = bfpair(o.x, o.y);
                        *(uint32_t*)&g_A2lo[ai] = bfpair_lo(o.x, o.y);
                    }
                }
            }
        }
    }
}

// ---------------- persistent tensor-core LSTM recurrence (R11/R12) ---------
#define RWS 520
#define RH_ELE (64 * RWS)
#define W_ELE  (32 * RWS)
#define RED_OFF_ELE (2 * RH_ELE + 2 * W_ELE)
#define PERS2_SMEM (RED_OFF_ELE * 2 + 8192)

__global__ __launch_bounds__(256, 1)
void pers_lstm2(const float* __restrict__ Whf, const float* __restrict__ Whb,
                const float* __restrict__ masks,
                const float* __restrict__ f_init, const float* __restrict__ b_init,
                int layer, int outSel, float* __restrict__ outExt)
{
    extern __shared__ __nv_bfloat16 sm2[];
    __nv_bfloat16* hhi = sm2;
    __nv_bfloat16* hlo = sm2 + RH_ELE;
    __nv_bfloat16* whi = sm2 + 2 * RH_ELE;
    __nv_bfloat16* wlo = whi + W_ELE;
    float* red = (float*)(sm2 + RED_OFF_ELE);

    const int dir = blockIdx.y;
    const float* Whh  = dir ? Whb : Whf;
    const float* gx   = dir ? g_gxb : g_gxf;
    const float* init = (dir ? b_init : f_init) + (size_t)layer * 2 * HID;
    float* outcat = sel_buf(outSel, outExt);

    const int tid = threadIdx.x, lane = tid & 31, wid = tid >> 5;
    const int kh = wid >> 2, mt = wid & 3;
    const int r = lane >> 2, cq = (lane & 3) * 2;
    const int hc0 = blockIdx.x * 8;

    for (int n = 0; n < 32; n++) {
        const float* src = Whh + (size_t)((n >> 3) * HID + hc0 + (n & 7)) * HID;
        for (int k = tid; k < HID; k += 256) {
            float vv = src[k];
            __nv_bfloat16 h = __float2bfloat16(vv);
            whi[n * RWS + k] = h;
            wlo[n * RWS + k] = __float2bfloat16(vv - __bfloat162float(h));
        }
    }

    const int b0 = mt * 16 + r, b1 = b0 + 8;
    const int hcol = hc0 + cq;
    float creg[4];
    creg[0] = init[HID + hcol]; creg[1] = init[HID + hcol + 1];
    creg[2] = creg[0]; creg[3] = creg[1];
    __syncthreads();

    for (int s = 0; s < T_SEQ; s++) {
        const int t = dir ? (T_SEQ - 1 - s) : s;
        const uint4* ghi = (const uint4*)g_hbf[dir][s & 1][0];
        const uint4* glo = (const uint4*)g_hbf[dir][s & 1][1];

        float2 gxv[4][2]; float mk0 = 0.f, mk1 = 0.f;
        if (kh == 0) {
            const size_t gb0 = ((size_t)t * BATCH + b0) * G4H + hcol;
            const size_t gb1 = ((size_t)t * BATCH + b1) * G4H + hcol;
            #pragma unroll
            for (int g = 0; g < 4; g++) {
                gxv[g][0] = __ldcg((const float2*)&gx[gb0 + g * HID]);
                gxv[g][1] = __ldcg((const float2*)&gx[gb1 + g * HID]);
            }
            mk0 = __ldg(&masks[t * BATCH + b0]);
            mk1 = __ldg(&masks[t * BATCH + b1]);
        }

        #pragma unroll
        for (int i = 0; i < 16; i += 4) {
            uint4 va[4], vb[4];
            #pragma unroll
            for (int j = 0; j < 4; j++) {
                const int u = (i + j) * 256 + tid;
                va[j] = __ldcg(ghi + u);
                vb[j] = __ldcg(glo + u);
            }
            #pragma unroll
            for (int j = 0; j < 4; j++) {
                const int u = (i + j) * 256 + tid;
                const int row = u >> 6, c16 = u & 63;
                *(uint4*)(hhi + row * RWS + c16 * 8) = va[j];
                *(uint4*)(hlo + row * RWS + c16 * 8) = vb[j];
            }
        }
        __syncthreads();

        float acc[4][4] = {};
        const int k0 = kh * 256;
        #pragma unroll 4
        for (int ks = 0; ks < 16; ks++) {
            const int kb = k0 + ks * 16;
            const __nv_bfloat16* ar = hhi + (mt * 16 + r) * RWS + kb + cq;
            const __nv_bfloat16* al = hlo + (mt * 16 + r) * RWS + kb + cq;
            uint32_t ahi4[4], alo4[4];
            ahi4[0] = *(const uint32_t*)(ar);
            ahi4[1] = *(const uint32_t*)(ar + 8 * RWS);
            ahi4[2] = *(const uint32_t*)(ar + 8);
            ahi4[3] = *(const uint32_t*)(ar + 8 * RWS + 8);
            alo4[0] = *(const uint32_t*)(al);
            alo4[1] = *(const uint32_t*)(al + 8 * RWS);
            alo4[2] = *(const uint32_t*)(al + 8);
            alo4[3] = *(const uint32_t*)(al + 8 * RWS + 8);
            #pragma unroll
            for (int nt = 0; nt < 4; nt++) {
                const __nv_bfloat16* br = whi + (nt * 8 + r) * RWS + kb + cq;
                const __nv_bfloat16* bl = wlo + (nt * 8 + r) * RWS + kb + cq;
                uint32_t bhi2[2], blo2[2];
                bhi2[0] = *(const uint32_t*)(br); bhi2[1] = *(const uint32_t*)(br + 8);
                blo2[0] = *(const uint32_t*)(bl); blo2[1] = *(const uint32_t*)(bl + 8);
                mma16816(acc[nt], ahi4, bhi2);
                mma16816(acc[nt], ahi4, blo2);
                mma16816(acc[nt], alo4, bhi2);
            }
        }

        if (kh == 1) {
            float4* rr = (float4*)red + ((mt << 5) + lane) * 4;
            #pragma unroll
            for (int nt = 0; nt < 4; nt++)
                rr[nt] = make_float4(acc[nt][0], acc[nt][1], acc[nt][2], acc[nt][3]);
        }
        __syncthreads();

        if (kh == 0) {
            const float4* rr = (const float4*)red + ((mt << 5) + lane) * 4;
            #pragma unroll
            for (int nt = 0; nt < 4; nt++) {
                float4 rv = rr[nt];
                acc[nt][0] += rv.x; acc[nt][1] += rv.y;
                acc[nt][2] += rv.z; acc[nt][3] += rv.w;
            }
            float hn[4];
            #pragma unroll
            for (int j = 0; j < 4; j++) {
                const int bi = j >> 1;
                const float gxi = (j & 1) ? gxv[0][bi].y : gxv[0][bi].x;
                const float gxF = (j & 1) ? gxv[1][bi].y : gxv[1][bi].x;
                const float gxg = (j & 1) ? gxv[2][bi].y : gxv[2][bi].x;
                const float gxo = (j & 1) ? gxv[3][bi].y : gxv[3][bi].x;
                const float mk  = bi ? mk1 : mk0;
                float ig = sigf(acc[0][j] + gxi);
                float fg = sigf(acc[1][j] + gxF);
                float tg = tanhf(acc[2][j] + gxg);
                float og = sigf(acc[3][j] + gxo);
                float cn = (fg * creg[j] + ig * tg) * mk;
                hn[j] = og * tanhf(cn) * mk;
                creg[j] = cn;
            }
            const size_t ob = (size_t)t * (BATCH * D2H) + dir * HID + hcol;
            __stcg((float2*)&outcat[ob + (size_t)b0 * D2H], make_float2(hn[0], hn[1]));
            __stcg((float2*)&outcat[ob + (size_t)b1 * D2H], make_float2(hn[2], hn[3]));
            __stcg((uint32_t*)&g_Ahi[ob + (size_t)b0 * D2H], bfpair(hn[0], hn[1]));
            __stcg((uint32_t*)&g_Alo[ob + (size_t)b0 * D2H], bfpair_lo(hn[0], hn[1]));
            __stcg((uint32_t*)&g_Ahi[ob + (size_t)b1 * D2H], bfpair(hn[2], hn[3]));
            __stcg((uint32_t*)&g_Alo[ob + (size_t)b1 * D2H], bfpair_lo(hn[2], hn[3]));

            __nv_bfloat16* dhi = g_hbf[dir][(s & 1) ^ 1][0];
            __nv_bfloat16* dlo = g_hbf[dir][(s & 1) ^ 1][1];
            #pragma unroll
            for (int half = 0; half < 2; half++) {
                float v0 = hn[half * 2], v1 = hn[half * 2 + 1];
                const int bb = half ? b1 : b0;
                __stcg((uint32_t*)&dhi[bb * HID + hcol], bfpair(v0, v1));
                __stcg((uint32_t*)&dlo[bb * HID + hcol], bfpair_lo(v0, v1));
            }
        }

        __threadfence();
        __syncthreads();
        if (tid == 0) {
            atomicAdd(&g_bar[dir], 1u);
            const unsigned target = (unsigned)NBLK_DIR * (unsigned)(s + 1);
            volatile unsigned* pb = &g_bar[dir];
            while (*pb < target) __nanosleep(32);
        }
        __syncthreads();
    }

    if (kh == 0) {
        *(float2*)&g_c[dir][b0 * HID + hcol] = make_float2(creg[0], creg[1]);
        *(float2*)&g_c[dir][b1 * HID + hcol] = make_float2(creg[2], creg[3]);
    }
}

// ---------------- small state kernels ----------------
__global__ void init_states_kernel(const float* __restrict__ f_init,
                                   const float* __restrict__ b_init, int layer)
{
    int idx = blockIdx.x * blockDim.x + threadIdx.x;
    if (idx < 2 && blockIdx.x == 0) g_bar[idx] = 0;
    if (idx >= BATCH * HID) return;
    int j = idx & (HID - 1);
    float fv = f_init[layer * 2 * HID + j];
    float bv = b_init[layer * 2 * HID + j];
    __nv_bfloat16 fh = __float2bfloat16(fv);
    __nv_bfloat16 bh = __float2bfloat16(bv);
    g_hbf[0][0][0][idx] = fh;
    g_hbf[0][0][1][idx] = __float2bfloat16(fv - __bfloat162float(fh));
    g_hbf[1][0][0][idx] = bh;
    g_hbf[1][0][1][idx] = __float2bfloat16(bv - __bfloat162float(bh));
}

__global__ void copy_states_kernel(float* __restrict__ hn, float* __restrict__ cn,
                                   int layer, int catSel)
{
    int idx = blockIdx.x * blockDim.x + threadIdx.x;
    if (idx >= BATCH * HID) return;
    int b = idx >> 9, j = idx & (HID - 1);
    const float* cat = sel_cbuf(catSel, nullptr);
    hn[(size_t)(2 * layer + 0) * BATCH * HID + idx] =
        cat[(size_t)(T_SEQ - 1) * (BATCH * D2H) + (size_t)b * D2H + j];
    hn[(size_t)(2 * layer + 1) * BATCH * HID + idx] =
        cat[(size_t)b * D2H + HID + j];
    cn[(size_t)(2 * layer + 0) * BATCH * HID + idx] = g_c[0][idx];
    cn[(size_t)(2 * layer + 1) * BATCH * HID + idx] = g_c[1][idx];
}

// ---------------- launcher ----------------
extern "C" void kernel_launch(void* const* d_in, const int* in_sizes, int n_in,
                              void* d_out, int out_size)
{
    (void)in_sizes; (void)n_in; (void)out_size;
    const float* x          = (const float*)d_in[0];
    const float* masks      = (const float*)d_in[1];
    const float* f_Wih0     = (const float*)d_in[2];
    const float* f_Wih_rest = (const float*)d_in[3];
    const float* f_Whh      = (const float*)d_in[4];
    const float* f_b        = (const float*)d_in[5];
    const float* b_Wih0     = (const float*)d_in[6];
    const float* b_Wih_rest = (const float*)d_in[7];
    const float* b_Whh      = (const float*)d_in[8];
    const float* b_b        = (const float*)d_in[9];
    const float* f_init     = (const float*)d_in[10];
    const float* b_init     = (const float*)d_in[11];
    const float* proj_W     = (const float*)d_in[12];
    const float* proj_b     = (const float*)d_in[13];

    float* out = (float*)d_out;                       // [T,B,2H]
    float* hn  = out + (size_t)MR * D2H;              // [6,B,H]
    float* cn  = hn + (size_t)6 * BATCH * HID;        // [6,B,H]

    cudaFuncSetAttribute(pers_lstm2,
                         cudaFuncAttributeMaxDynamicSharedMemorySize, PERS2_SMEM);
    cudaFuncSetAttribute(mma_gemm<0>,
                         cudaFuncAttributeMaxDynamicSharedMemorySize, MG_SMEM);
    cudaFuncSetAttribute(mma_gemm<1>,
                         cudaFuncAttributeMaxDynamicSharedMemorySize, MG_SMEM);

    const int catSel[3] = { 1, 2, 1 };   // float cat: bufA, bufB, bufA
    const int Kin[3]    = { 512, 1024, 1024 };
    const int gateAPair[3] = { 1, 1, 2 };

    for (int layer = 0; layer < 3; layer++) {
        const int K = Kin[layer];
        init_states_kernel<<<128, 256>>>(f_init, b_init, layer);

        if (layer == 0)
            split_convert<<<1024, 256>>>(x, 0, 0, 0, ((size_t)MR * K) / 4);
        const float* Wf = (layer == 0) ? f_Wih0 : f_Wih_rest + (size_t)(layer - 1) * G4H * D2H;
        const float* Wb = (layer == 0) ? b_Wih0 : b_Wih_rest + (size_t)(layer - 1) * G4H * D2H;
        split_convert<<<512, 256>>>(Wf, 0, 1, 0,               ((size_t)G4H * K) / 4);
        split_convert<<<512, 256>>>(Wb, 0, 1, (size_t)G4H * K, ((size_t)G4H * K) / 4);

        // ---- gate pre-activations ----
        mma_gemm<0><<<dim3(G4H / 128, MR / 128, 2), 256, MG_SMEM>>>(
            f_b + (size_t)layer * G4H, b_b + (size_t)layer * G4H,
            nullptr, 4 /*gxf*/, nullptr, 5 /*gxb*/,
            nullptr, 0, nullptr, 0,
            gateAPair[layer], 0,
            G4H, K);

        // ---- recurrence (writes cat float + bf16 pair1) ----
        const float* Whf = f_Whh + (size_t)layer * G4H * HID;
        const float* Whb = b_Whh + (size_t)layer * G4H * HID;
        pers_lstm2<<<dim3(NBLK_DIR, 2), 256, PERS2_SMEM>>>(
            Whf, Whb, masks, f_init, b_init, layer, catSel[layer], nullptr);

        copy_states_kernel<<<128, 256>>>(hn, cn, layer, catSel[layer]);

        // ---- highway projection ----
        if (layer > 0) {
            split_convert<<<512, 256>>>(proj_W + (size_t)(layer - 1) * D2H * D2H, 0,
                                        1, 0, ((size_t)D2H * D2H) / 4);
            mma_gemm<1><<<dim3(D2H / 128, MR / 128, 1), 256, MG_SMEM>>>(
                proj_b + (size_t)(layer - 1) * D2H, nullptr,
                (layer == 2) ? out : nullptr, (layer == 1) ? 3 : 0,
                nullptr, 0,
                nullptr, catSel[layer],
                nullptr, (layer == 1) ? 1 : 3,
                1, (layer == 1) ? 2 : 0,
                D2H, D2H);
        }
    }
}